// round 1
// baseline (speedup 1.0000x reference)
#include <cuda_runtime.h>
#include <cstdint>

// Problem dims (fixed)
#define Bb 32
#define Ss 64
#define Tt 64
#define Dd 256
#define Hh 512
#define Vv 32000

// ---------------- device scratch (no allocations allowed) ----------------
__device__ float g_gi [2048 * 1536];   // reused: gi_e0 -> gi_e1 -> gi_dec_emb
__device__ float g_y0 [2048 * 512];    // encoder layer0 outputs [s][b][512]
__device__ float g_enc[2048 * 512];    // encoder outputs [b][s][512]
__device__ float g_U  [2048 * 512];    // enc part of attn energy [b][s][512]
__device__ float g_H1 [2048 * 512];    // decoder top hidden per step [t][b][512]
__device__ float g_hA [2 * Bb * Hh];   // layer0 / decoder h0 (ping-pong)
__device__ float g_hB [2 * Bb * Hh];   // layer1 / decoder h1 (ping-pong)
__device__ float g_q  [Bb * Hh];
__device__ float g_ctx[Bb * Hh];
__device__ int   g_idx[2048];

__device__ __forceinline__ float fast_sigmoid(float x) {
    return 1.f / (1.f + __expf(-x));
}
__device__ __forceinline__ float fast_tanh(float x) {
    float t = __expf(-2.f * fabsf(x));
    float r = (1.f - t) / (1.f + t);
    return copysignf(r, x);
}

// ---------------- gather index builder ----------------
__global__ void build_idx_kernel(const int* __restrict__ in_seq,
                                 const int* __restrict__ tg_seq,
                                 int* __restrict__ idx, int mode) {
    int m = blockIdx.x * 256 + threadIdx.x;
    if (m >= 2048) return;
    int b = m & 31, t = m >> 5;
    if (mode == 0) idx[m] = in_seq[b * 64 + t];                    // encoder: x[s,b]
    else           idx[m] = (t == 0) ? 0 : tg_seq[b * 64 + t - 1]; // decoder teacher forcing
}

// ---------------- generic SGEMM-NT: C[M,N] = A[M,K] * B[N,K]^T (+bias) ----
// 128x128 tile, 256 threads, 8x8 per thread. M,N multiples of 128, K of 8.
__global__ __launch_bounds__(256)
void gemm_nt_kernel(const float* __restrict__ A, int lda,
                    const float* __restrict__ Bm, int ldb,
                    const float* __restrict__ bias,
                    float* __restrict__ C, int N, int K,
                    const int* __restrict__ gidx, int outmode) {
    const int tid = threadIdx.x;
    const int bn = blockIdx.x * 128;
    const int bm = blockIdx.y * 128;
    __shared__ float As[8][132];
    __shared__ float Bs[8][132];
    const int tx = tid & 15, ty = tid >> 4;
    float acc[8][8];
#pragma unroll
    for (int i = 0; i < 8; i++)
#pragma unroll
        for (int j = 0; j < 8; j++) acc[i][j] = 0.f;

    const int lrow = tid >> 1;
    const int lk4  = (tid & 1) * 4;
    int arow = gidx ? gidx[bm + lrow] : (bm + lrow);
    const float* Ap = A  + (size_t)arow        * lda + lk4;
    const float* Bp = Bm + (size_t)(bn + lrow) * ldb + lk4;

    for (int kc = 0; kc < K; kc += 8) {
        float4 av = *(const float4*)(Ap + kc);
        float4 bv = *(const float4*)(Bp + kc);
        As[lk4 + 0][lrow] = av.x; As[lk4 + 1][lrow] = av.y;
        As[lk4 + 2][lrow] = av.z; As[lk4 + 3][lrow] = av.w;
        Bs[lk4 + 0][lrow] = bv.x; Bs[lk4 + 1][lrow] = bv.y;
        Bs[lk4 + 2][lrow] = bv.z; Bs[lk4 + 3][lrow] = bv.w;
        __syncthreads();
#pragma unroll
        for (int kk = 0; kk < 8; kk++) {
            float a[8], b[8];
#pragma unroll
            for (int i = 0; i < 8; i++) {
                a[i] = As[kk][ty + 16 * i];
                b[i] = Bs[kk][tx + 16 * i];
            }
#pragma unroll
            for (int i = 0; i < 8; i++)
#pragma unroll
                for (int j = 0; j < 8; j++)
                    acc[i][j] = fmaf(a[i], b[j], acc[i][j]);
        }
        __syncthreads();
    }
#pragma unroll
    for (int i = 0; i < 8; i++) {
        int m = bm + ty + 16 * i;
        int orow = (outmode == 1) ? ((m & 31) * 64 + (m >> 5)) : m; // [t*32+b] -> [b*64+t]
        float* crow = C + (size_t)orow * N;
#pragma unroll
        for (int j = 0; j < 8; j++) {
            int n = bn + tx + 16 * j;
            float v = acc[i][j];
            if (bias) v += bias[n];
            crow[n] = v;
        }
    }
}

// ---------------- fused GRU cell step ----------------
// Thread (b, jl): computes the 3 recurrent dots gh_{r,z,n}[b,j] (and optionally
// the 3 input dots from vector x), applies gate math, writes h_next.
// grid = 128 blocks (4 j per block), block = 128 threads (32 b x 4 jl).
template <bool HASX>
__global__ __launch_bounds__(128)
void gru_cell_kernel(const float* __restrict__ x,
                     const float* __restrict__ Wx, int ldwx, int wxoff,
                     const float* __restrict__ bx,
                     const float* __restrict__ gi_pre,   // [32][1536] incl. bias, or null
                     const float* __restrict__ h,        // [32][512] prev
                     const float* __restrict__ Wh,       // [1536][512]
                     const float* __restrict__ bh,
                     float* __restrict__ hout,           // [32][512] next
                     float* __restrict__ ystore, int ysB) {
    const int tid = threadIdx.x;
    const int b  = tid & 31;
    const int jl = tid >> 5;
    const int jbase = blockIdx.x * 4;
    const int j = jbase + jl;
    __shared__ float hs[32][65];
    __shared__ float xs[HASX ? 32 : 1][65];
    __shared__ float ws[24][64];
    float acch0 = 0, acch1 = 0, acch2 = 0;
    float accx0 = 0, accx1 = 0, accx2 = 0;

    for (int kc = 0; kc < 512; kc += 64) {
#pragma unroll
        for (int l = 0; l < 16; l++) {
            int i = tid + l * 128, bb = i >> 6, kk = i & 63;
            hs[bb][kk] = h[bb * 512 + kc + kk];
            if (HASX) xs[bb][kk] = x[bb * 512 + kc + kk];
        }
#pragma unroll
        for (int l = 0; l < 6; l++) {
            int i = tid + l * 128, r = i >> 6, kk = i & 63;
            int row = (r >> 2) * 512 + jbase + (r & 3);
            ws[r][kk] = Wh[row * 512 + kc + kk];
            if (HASX) ws[12 + r][kk] = Wx[row * ldwx + wxoff + kc + kk];
        }
        __syncthreads();
#pragma unroll
        for (int kk = 0; kk < 64; kk++) {
            float hv = hs[b][kk];
            acch0 = fmaf(hv, ws[jl][kk],      acch0);
            acch1 = fmaf(hv, ws[4  + jl][kk], acch1);
            acch2 = fmaf(hv, ws[8  + jl][kk], acch2);
            if (HASX) {
                float xv = xs[b][kk];
                accx0 = fmaf(xv, ws[12 + jl][kk], accx0);
                accx1 = fmaf(xv, ws[16 + jl][kk], accx1);
                accx2 = fmaf(xv, ws[20 + jl][kk], accx2);
            }
        }
        __syncthreads();
    }

    float gh0 = acch0 + bh[j];
    float gh1 = acch1 + bh[512 + j];
    float gh2 = acch2 + bh[1024 + j];
    float gi0, gi1, gi2;
    if (gi_pre) {
        gi0 = gi_pre[b * 1536 + j]        + accx0;
        gi1 = gi_pre[b * 1536 + 512 + j]  + accx1;
        gi2 = gi_pre[b * 1536 + 1024 + j] + accx2;
    } else {
        gi0 = accx0 + bx[j];
        gi1 = accx1 + bx[512 + j];
        gi2 = accx2 + bx[1024 + j];
    }
    float r = fast_sigmoid(gi0 + gh0);
    float z = fast_sigmoid(gi1 + gh1);
    float n = fast_tanh(gi2 + r * gh2);
    float hn = (1.f - z) * n + z * h[b * 512 + j];
    hout[b * 512 + j] = hn;
    if (ystore) ystore[b * ysB + j] = hn;
}

// ---------------- q = h1 @ W_attn[:, :512]^T ----------------
// grid = 32 blocks (16 n each), block = 256 threads (32 b x 8 nl), 2 n/thread.
__global__ __launch_bounds__(256)
void q_kernel(const float* __restrict__ h1, const float* __restrict__ W_attn) {
    const int tid = threadIdx.x;
    const int b  = tid & 31;
    const int nl = tid >> 5;  // 0..7
    const int nbase = blockIdx.x * 16;
    __shared__ float hs[32][65];
    __shared__ float ws[16][64];
    float acc0 = 0, acc1 = 0;
    for (int kc = 0; kc < 512; kc += 64) {
#pragma unroll
        for (int l = 0; l < 8; l++) {
            int i = tid + l * 256, bb = i >> 6, kk = i & 63;
            hs[bb][kk] = h1[bb * 512 + kc + kk];
        }
#pragma unroll
        for (int l = 0; l < 4; l++) {
            int i = tid + l * 256, r = i >> 6, kk = i & 63;
            ws[r][kk] = W_attn[(nbase + r) * 1024 + kc + kk];
        }
        __syncthreads();
#pragma unroll
        for (int kk = 0; kk < 64; kk++) {
            float hv = hs[b][kk];
            acc0 = fmaf(hv, ws[nl][kk],     acc0);
            acc1 = fmaf(hv, ws[8 + nl][kk], acc1);
        }
        __syncthreads();
    }
    g_q[b * 512 + nbase + nl]     = acc0;
    g_q[b * 512 + nbase + 8 + nl] = acc1;
}

// ---------------- attention: scores -> softmax -> context ----------------
// grid = 32 (one block per batch), block = 256 threads.
__global__ __launch_bounds__(256)
void attn_kernel(const float* __restrict__ v_attn) {
    __shared__ float qv[512];
    __shared__ float vv[512];
    __shared__ float sc[64];
    __shared__ float aw[64];
    const int b = blockIdx.x;
    const int tid = threadIdx.x;
    for (int i = tid; i < 512; i += 256) {
        qv[i] = g_q[b * 512 + i];
        vv[i] = v_attn[i];
    }
    __syncthreads();
    const int w = tid >> 5, lane = tid & 31;
    // scores: warp w handles 8 s values
    for (int ss = 0; ss < 8; ss++) {
        int s = w * 8 + ss;
        const float* Urow = g_U + (size_t)(b * 64 + s) * 512;
        float p = 0.f;
        for (int n = lane; n < 512; n += 32)
            p += vv[n] * fast_tanh(qv[n] + Urow[n]);
#pragma unroll
        for (int o = 16; o; o >>= 1) p += __shfl_xor_sync(0xffffffffu, p, o);
        if (lane == 0) sc[s] = p;
    }
    __syncthreads();
    if (w == 0) {
        float v0 = sc[lane], v1 = sc[lane + 32];
        float mx = fmaxf(v0, v1);
#pragma unroll
        for (int o = 16; o; o >>= 1) mx = fmaxf(mx, __shfl_xor_sync(0xffffffffu, mx, o));
        float e0 = __expf(v0 - mx), e1 = __expf(v1 - mx);
        float sm = e0 + e1;
#pragma unroll
        for (int o = 16; o; o >>= 1) sm += __shfl_xor_sync(0xffffffffu, sm, o);
        float inv = 1.f / sm;
        aw[lane]      = e0 * inv;
        aw[lane + 32] = e1 * inv;
    }
    __syncthreads();
    for (int n = tid; n < 512; n += 256) {
        const float* erow = g_enc + (size_t)b * 64 * 512 + n;
        float acc = 0.f;
#pragma unroll 8
        for (int s = 0; s < 64; s++) acc = fmaf(aw[s], erow[s * 512], acc);
        g_ctx[b * 512 + n] = acc;
    }
}

// ---------------- host orchestration ----------------
extern "C" void kernel_launch(void* const* d_in, const int* in_sizes, int n_in,
                              void* d_out, int out_size) {
    (void)in_sizes; (void)n_in; (void)out_size;
    const int*   in_seq = (const int*)d_in[0];
    const int*   tg_seq = (const int*)d_in[1];
    const float* E_enc  = (const float*)d_in[2];
    const float* Wx_e0  = (const float*)d_in[3];
    const float* Wh_e0  = (const float*)d_in[4];
    const float* bx_e0  = (const float*)d_in[5];
    const float* bh_e0  = (const float*)d_in[6];
    const float* Wx_e1  = (const float*)d_in[7];
    const float* Wh_e1  = (const float*)d_in[8];
    const float* bx_e1  = (const float*)d_in[9];
    const float* bh_e1  = (const float*)d_in[10];
    const float* E_dec  = (const float*)d_in[11];
    const float* W_attn = (const float*)d_in[12];
    const float* b_attn = (const float*)d_in[13];
    const float* v_attn = (const float*)d_in[14];
    const float* Wx_d0  = (const float*)d_in[15];
    const float* Wh_d0  = (const float*)d_in[16];
    const float* bx_d0  = (const float*)d_in[17];
    const float* bh_d0  = (const float*)d_in[18];
    const float* Wx_d1  = (const float*)d_in[19];
    const float* Wh_d1  = (const float*)d_in[20];
    const float* bx_d1  = (const float*)d_in[21];
    const float* bh_d1  = (const float*)d_in[22];
    const float* W_out  = (const float*)d_in[23];
    const float* b_out  = (const float*)d_in[24];
    float* out = (float*)d_out;

    float *gi, *y0, *enc, *U, *H1, *hA, *hB, *ctxp;
    int* idx;
    cudaGetSymbolAddress((void**)&gi,   g_gi);
    cudaGetSymbolAddress((void**)&y0,   g_y0);
    cudaGetSymbolAddress((void**)&enc,  g_enc);
    cudaGetSymbolAddress((void**)&U,    g_U);
    cudaGetSymbolAddress((void**)&H1,   g_H1);
    cudaGetSymbolAddress((void**)&hA,   g_hA);
    cudaGetSymbolAddress((void**)&hB,   g_hB);
    cudaGetSymbolAddress((void**)&ctxp, g_ctx);
    cudaGetSymbolAddress((void**)&idx,  g_idx);

    cudaMemsetAsync(hA, 0, 2 * Bb * Hh * sizeof(float));
    cudaMemsetAsync(hB, 0, 2 * Bb * Hh * sizeof(float));

    // ---- encoder ----
    build_idx_kernel<<<8, 256>>>(in_seq, tg_seq, idx, 0);
    // gi_e0 = gather(E_enc) @ Wx_e0^T + bx_e0   [2048,1536] K=256
    gemm_nt_kernel<<<dim3(12, 16), 256>>>(E_enc, 256, Wx_e0, 256, bx_e0,
                                          gi, 1536, 256, idx, 0);
    for (int s = 0; s < 64; s++) {
        int par = s & 1;
        gru_cell_kernel<false><<<128, 128>>>(
            nullptr, nullptr, 0, 0, nullptr,
            gi + (size_t)s * 32 * 1536,
            hA + par * 16384, Wh_e0, bh_e0, hA + (par ^ 1) * 16384,
            y0 + (size_t)s * 16384, 512);
    }
    // gi_e1 = y0 @ Wx_e1^T + bx_e1   [2048,1536] K=512
    gemm_nt_kernel<<<dim3(12, 16), 256>>>(y0, 512, Wx_e1, 512, bx_e1,
                                          gi, 1536, 512, nullptr, 0);
    for (int s = 0; s < 64; s++) {
        int par = s & 1;
        gru_cell_kernel<false><<<128, 128>>>(
            nullptr, nullptr, 0, 0, nullptr,
            gi + (size_t)s * 32 * 1536,
            hB + par * 16384, Wh_e1, bh_e1, hB + (par ^ 1) * 16384,
            enc + (size_t)s * 512, 32768);  // enc_out[b][s][j]
    }
    // U = enc_out @ W_attn[:, 512:]^T + b_attn   [2048,512] K=512
    gemm_nt_kernel<<<dim3(4, 16), 256>>>(enc, 512, W_attn + 512, 1024, b_attn,
                                         U, 512, 512, nullptr, 0);
    // decoder embedding-part of gi_d0 (includes bx_d0)
    build_idx_kernel<<<8, 256>>>(in_seq, tg_seq, idx, 1);
    gemm_nt_kernel<<<dim3(12, 16), 256>>>(E_dec, 256, Wx_d0, 768, bx_d0,
                                          gi, 1536, 256, idx, 0);

    // ---- decoder (teacher forcing) ----
    for (int t = 0; t < 64; t++) {
        int par = t & 1;
        q_kernel<<<32, 256>>>(hB + par * 16384, W_attn);
        attn_kernel<<<32, 256>>>(v_attn);
        // d0: x = ctx (uses Wx_d0 cols 256..768), gi_pre = emb part
        gru_cell_kernel<true><<<128, 128>>>(
            ctxp, Wx_d0, 768, 256, nullptr,
            gi + (size_t)t * 32 * 1536,
            hA + par * 16384, Wh_d0, bh_d0, hA + (par ^ 1) * 16384,
            nullptr, 0);
        // d1: x = h0_new, full Wx_d1
        gru_cell_kernel<true><<<128, 128>>>(
            hA + (par ^ 1) * 16384, Wx_d1, 512, 0, bx_d1,
            nullptr,
            hB + par * 16384, Wh_d1, bh_d1, hB + (par ^ 1) * 16384,
            H1 + (size_t)t * 16384, 512);
    }

    // ---- logits: out[b,t,:] = H1[t,b,:] @ W_out^T + b_out  [2048,32000] K=512
    gemm_nt_kernel<<<dim3(250, 16), 256>>>(H1, 512, W_out, 512, b_out,
                                           out, 32000, 512, nullptr, 1);
}